// round 4
// baseline (speedup 1.0000x reference)
#include <cuda_runtime.h>
#include <cuda_bf16.h>
#include <math.h>

// ---------------------------------------------------------------------------
#define BB 512
#define VV 6890
#define NJ 24
#define NBETA 10
#define NP 207
#define NJO 19
#define VC (VV*3)              // 20670
#define KTOT 217
#define KPAD 224               // 7*32
#define JNT_OFF  (BB*VC)
#define ROT_OFF  (JNT_OFF + BB*NJO*3)

typedef unsigned long long u64;

__device__ __forceinline__ u64 ffma2(u64 a, u64 b, u64 c) {
    u64 d;
    asm("fma.rn.f32x2 %0, %1, %2, %3;" : "=l"(d) : "l"(a), "l"(b), "l"(c));
    return d;
}
__device__ __forceinline__ u64 pack2(float lo, float hi) {
    u64 d;
    asm("mov.b64 %0, {%1, %2};" : "=l"(d) : "f"(lo), "f"(hi));
    return d;
}
__device__ __forceinline__ float2 unpack2(u64 v) {
    float2 f;
    asm("mov.b64 {%0, %1}, %2;" : "=f"(f.x), "=f"(f.y) : "l"(v));
    return f;
}

// ---------------------------------------------------------------------------
__device__ float g_pfT[KPAD * BB];        // pose-feature+beta, [k][b]
__device__ float g_A[BB * NJ * 12];       // A' 3x4 per (b,j)
__device__ float g_jmp[NJ * 8 * 33];
__device__ float g_jm[NJ * 33];
__device__ float g_jpart[BB * 14 * 57];

// ---------------------------------------------------------------------------
// Kernel 0: batch-independent precompute for rest joints
// ---------------------------------------------------------------------------
__global__ void __launch_bounds__(128) k_jm(const float* __restrict__ vt,
                                            const float* __restrict__ shp,
                                            const float* __restrict__ sr)
{
    int j = blockIdx.x, part = blockIdx.y;
    int vs = part * 862;
    int ve = vs + 862; if (ve > VV) ve = VV;

    float acc[33];
    #pragma unroll
    for (int i = 0; i < 33; ++i) acc[i] = 0.f;

    for (int v = vs + threadIdx.x; v < ve; v += 128) {
        float w = sr[v * NJ + j];
        acc[0] += vt[v*3+0] * w;
        acc[1] += vt[v*3+1] * w;
        acc[2] += vt[v*3+2] * w;
        #pragma unroll
        for (int k = 0; k < NBETA; ++k) {
            const float* s = shp + k * VC + v * 3;
            acc[3+k*3+0] += s[0] * w;
            acc[3+k*3+1] += s[1] * w;
            acc[3+k*3+2] += s[2] * w;
        }
    }
    #pragma unroll
    for (int m = 16; m > 0; m >>= 1)
        #pragma unroll
        for (int i = 0; i < 33; ++i)
            acc[i] += __shfl_xor_sync(0xffffffffu, acc[i], m);

    __shared__ float s[4][33];
    int wid = threadIdx.x >> 5, lane = threadIdx.x & 31;
    if (lane == 0)
        #pragma unroll
        for (int i = 0; i < 33; ++i) s[wid][i] = acc[i];
    __syncthreads();
    if (threadIdx.x < 33) {
        float t = s[0][threadIdx.x] + s[1][threadIdx.x] + s[2][threadIdx.x] + s[3][threadIdx.x];
        g_jmp[(j*8 + part)*33 + threadIdx.x] = t;
    }
}

__global__ void k_jmred()
{
    int i = blockIdx.x * blockDim.x + threadIdx.x;
    if (i < NJ * 33) {
        int jj = i / 33, r = i % 33;
        float t = 0.f;
        #pragma unroll
        for (int p = 0; p < 8; ++p) t += g_jmp[(jj*8 + p)*33 + r];
        g_jm[i] = t;
    }
}

// ---------------------------------------------------------------------------
// Kernel 1: fused Rodrigues + kinematic chain. 32 batches per block.
// Rodrigues results staged in smem so the serial chain reads at LDS latency.
// ---------------------------------------------------------------------------
__global__ void __launch_bounds__(96) k_rotchain(const float* __restrict__ inp,
                                                 float* __restrict__ out)
{
    const int PAR[NJ] = {0,0,0,0,1,2,3,4,5,6,7,8,9,9,9,12,13,14,16,17,18,19,20,21};
    __shared__ float s_jm[NJ * 33];        // 792
    __shared__ float sJ[32][NJ*3];         // 2304
    __shared__ float sR[32][NJ*9];         // 6912

    const int tid = threadIdx.x;
    const int b0 = blockIdx.x * 32;

    for (int i = tid; i < NJ*33; i += 96) s_jm[i] = g_jm[i];

    // Rodrigues: 768 (bl,j) items, 8 per thread
    for (int i = tid; i < 32*NJ; i += 96) {
        int bl = i / NJ, j = i % NJ;
        int b = b0 + bl;
        float rx = inp[b*82 + j*3 + 0];
        float ry = inp[b*82 + j*3 + 1];
        float rz = inp[b*82 + j*3 + 2];
        float ax = rx + 1e-8f, ay = ry + 1e-8f, az = rz + 1e-8f;
        float ang = sqrtf(ax*ax + ay*ay + az*az);
        float inv = 1.0f / ang;
        float nx = rx * inv, ny = ry * inv, nz = rz * inv;
        float c = cosf(ang), sn = sinf(ang), ic = 1.0f - c;
        float R[9];
        R[0] = c + ic*nx*nx;     R[1] = ic*nx*ny - sn*nz; R[2] = ic*nx*nz + sn*ny;
        R[3] = ic*ny*nx + sn*nz; R[4] = c + ic*ny*ny;     R[5] = ic*ny*nz - sn*nx;
        R[6] = ic*nz*nx - sn*ny; R[7] = ic*nz*ny + sn*nx; R[8] = c + ic*nz*nz;

        float* ro = out + ROT_OFF + (size_t)b*(NJ*9) + j*9;
        #pragma unroll
        for (int e = 0; e < 9; ++e) { ro[e] = R[e]; sR[bl][j*9+e] = R[e]; }

        if (j > 0) {
            int base = (j-1) * 9;
            #pragma unroll
            for (int e = 0; e < 9; ++e)
                g_pfT[(base + e) * BB + b] = R[e] - ((e==0||e==4||e==8) ? 1.0f : 0.0f);
        }
    }
    __syncthreads();

    // rest joints for 32 batches
    for (int i = tid; i < 32*NJ*3; i += 96) {
        int bl = i / 72, rem = i % 72;
        int j = rem / 3, c = rem % 3;
        int b = b0 + bl;
        float t = s_jm[j*33 + c];
        #pragma unroll
        for (int k = 0; k < NBETA; ++k)
            t = fmaf(inp[b*82 + 72 + k], s_jm[j*33 + 3 + k*3 + c], t);
        sJ[bl][j*3 + c] = t;
    }
    __syncthreads();

    const int bl = tid / 3;
    const int r  = tid % 3;
    const int b  = b0 + bl;
    const float* Rb = sR[bl];

    float row[NJ][3];
    float tw[NJ];
    row[0][0] = Rb[r*3+0]; row[0][1] = Rb[r*3+1]; row[0][2] = Rb[r*3+2];
    tw[0] = sJ[bl][r];

    #pragma unroll
    for (int j = 1; j < NJ; ++j) {
        const int p = PAR[j];
        float t0 = sJ[bl][j*3+0] - sJ[bl][p*3+0];
        float t1 = sJ[bl][j*3+1] - sJ[bl][p*3+1];
        float t2 = sJ[bl][j*3+2] - sJ[bl][p*3+2];
        float p0 = row[p][0], p1 = row[p][1], p2 = row[p][2];
        row[j][0] = p0*Rb[j*9+0] + p1*Rb[j*9+3] + p2*Rb[j*9+6];
        row[j][1] = p0*Rb[j*9+1] + p1*Rb[j*9+4] + p2*Rb[j*9+7];
        row[j][2] = p0*Rb[j*9+2] + p1*Rb[j*9+5] + p2*Rb[j*9+8];
        tw[j] = p0*t0 + p1*t1 + p2*t2 + tw[p];
    }

    float* Ao = g_A + (size_t)b * (NJ*12);
    #pragma unroll
    for (int j = 0; j < NJ; ++j) {
        float tp = tw[j] - (row[j][0]*sJ[bl][j*3+0] + row[j][1]*sJ[bl][j*3+1] + row[j][2]*sJ[bl][j*3+2]);
        float4 st = make_float4(row[j][0], row[j][1], row[j][2], tp);
        *reinterpret_cast<float4*>(&Ao[j*12 + r*4]) = st;
    }

    if (r == 0) {
        #pragma unroll
        for (int k = 0; k < NBETA; ++k) g_pfT[(NP + k)*BB + b] = inp[b*82 + 72 + k];
        #pragma unroll
        for (int k = KTOT; k < KPAD; ++k) g_pfT[k*BB + b] = 0.0f;
    }
}

// ---------------------------------------------------------------------------
// Kernel 2: fused blendshape GEMM + LBS skinning (FMA-bound layout).
// Block tile: 64 batches x 96 cols (32 verts). 128 threads.
//   cgrp = (lane&7) + 8*(warp&1)  in 0..15  -> 6 cols (2 verts)
//   bgrp = (lane>>3) + 4*(warp>>1) in 0..7  -> 8 batches
// Accumulators pack BATCH pairs (pf pairs come naturally from g_pfT);
// the d operand is stored lane-duplicated in smem. Within a warp, d loads
// broadcast 4-way and pf loads broadcast 8-way -> crossbar << FMA pipe.
// ---------------------------------------------------------------------------
__global__ void __launch_bounds__(128) k_main(const float* __restrict__ posedirs,
                                              const float* __restrict__ shapes,
                                              const float* __restrict__ lbs,
                                              const float* __restrict__ vtempl,
                                              float* __restrict__ out)
{
    __shared__ __align__(16) float smem[10080];   // 40.3 KB union

    const int b0   = blockIdx.y * 64;
    const int col0 = blockIdx.x * 96;
    const int v0   = blockIdx.x * 32;
    const int tid  = threadIdx.x;
    const int lane = tid & 31;
    const int warp = tid >> 5;
    const int cgrp = (lane & 7) + ((warp & 1) << 3);   // 0..15
    const int bgrp = (lane >> 3) + ((warp >> 1) << 2); // 0..7

    u64 acc[24];                       // [cc][bp] = cc*4+bp ; packs batch pairs
    const u64 z2 = pack2(0.f, 0.f);
    #pragma unroll
    for (int i = 0; i < 24; ++i) acc[i] = z2;

    u64*   s_pdd = reinterpret_cast<u64*>(smem);   // [32][96] dup pairs (24 KB)
    float* s_pf  = smem + 6144;                    // [32][64] (8 KB)

    for (int kt = 0; kt < 7; ++kt) {
        // pf tile: 32 k x 64 b, coalesced float4
        #pragma unroll
        for (int i = tid; i < 512; i += 128) {
            int k = i >> 4, q = i & 15;
            *reinterpret_cast<float4*>(&s_pf[k*64 + q*4]) =
                *reinterpret_cast<const float4*>(&g_pfT[(kt*32 + k)*BB + b0 + q*4]);
        }
        // d tile: 32 k x 96 cols, duplicated into u64
        #pragma unroll
        for (int i = tid; i < 1536; i += 128) {
            int k = i / 48, q = i % 48;
            int kg = kt*32 + k;
            int cg = col0 + q*2;
            float2 val = make_float2(0.f, 0.f);
            if (cg < VC) {
                if (kg < NP)
                    val = *reinterpret_cast<const float2*>(posedirs + (size_t)kg*VC + cg);
                else if (kg < KTOT)
                    val = *reinterpret_cast<const float2*>(shapes + (size_t)(kg-NP)*VC + cg);
            }
            s_pdd[k*96 + q*2 + 0] = pack2(val.x, val.x);
            s_pdd[k*96 + q*2 + 1] = pack2(val.y, val.y);
        }
        __syncthreads();

        #pragma unroll
        for (int k = 0; k < 32; ++k) {
            const u64* pf = reinterpret_cast<const u64*>(s_pf + k*64 + (bgrp << 3));
            u64 p0 = pf[0], p1 = pf[1], p2 = pf[2], p3 = pf[3];
            const u64* dd = s_pdd + k*96 + cgrp*6;
            #pragma unroll
            for (int cc = 0; cc < 6; ++cc) {
                u64 d = dd[cc];
                acc[cc*4+0] = ffma2(p0, d, acc[cc*4+0]);
                acc[cc*4+1] = ffma2(p1, d, acc[cc*4+1]);
                acc[cc*4+2] = ffma2(p2, d, acc[cc*4+2]);
                acc[cc*4+3] = ffma2(p3, d, acc[cc*4+3]);
            }
        }
        __syncthreads();
    }

    // ---- epilogue ----
    float* s_w  = smem + 9216;   // [32 verts][24]
    float* s_vt = smem + 9984;   // [96]
    for (int i = tid; i < 768; i += 128) {
        int v = v0 + i/24;
        s_w[i] = (v < VV) ? lbs[v*NJ + (i % 24)] : 0.f;
    }
    if (tid < 96) {
        int cg = col0 + tid;
        s_vt[tid] = (cg < VC) ? vtempl[cg] : 0.f;
    }

    const int v0l = cgrp * 2;
    const int vg0 = v0 + v0l;
    const int vg1 = vg0 + 1;

    #pragma unroll
    for (int pass = 0; pass < 2; ++pass) {
        __syncthreads();
        // stage A' for 32 batches (9216 floats)
        const float4* gA4 = reinterpret_cast<const float4*>(g_A + (size_t)(b0 + pass*32)*288);
        #pragma unroll
        for (int i = 0; i < 18; ++i)
            reinterpret_cast<float4*>(smem)[tid + 128*i] = gA4[tid + 128*i];
        __syncthreads();

        if ((bgrp >> 2) != pass) continue;

        const int lb = (bgrp & 3) * 8;
        #pragma unroll
        for (int bp = 0; bp < 4; ++bp) {
            #pragma unroll
            for (int half = 0; half < 2; ++half) {
                const int ab = lb + bp*2 + half;
                const int b = b0 + pass*32 + ab;
                const u64* Ar = reinterpret_cast<const u64*>(smem + ab*288);
                u64 T0[6], T1[6];
                #pragma unroll
                for (int i = 0; i < 6; ++i) { T0[i] = z2; T1[i] = z2; }
                #pragma unroll
                for (int j = 0; j < NJ; ++j) {
                    u64 a0 = Ar[j*6+0], a1 = Ar[j*6+1], a2 = Ar[j*6+2];
                    u64 a3 = Ar[j*6+3], a4 = Ar[j*6+4], a5 = Ar[j*6+5];
                    float w0 = s_w[(v0l+0)*24 + j];
                    float w1 = s_w[(v0l+1)*24 + j];
                    u64 w0d = pack2(w0, w0);
                    u64 w1d = pack2(w1, w1);
                    T0[0] = ffma2(w0d, a0, T0[0]); T0[1] = ffma2(w0d, a1, T0[1]);
                    T0[2] = ffma2(w0d, a2, T0[2]); T0[3] = ffma2(w0d, a3, T0[3]);
                    T0[4] = ffma2(w0d, a4, T0[4]); T0[5] = ffma2(w0d, a5, T0[5]);
                    T1[0] = ffma2(w1d, a0, T1[0]); T1[1] = ffma2(w1d, a1, T1[1]);
                    T1[2] = ffma2(w1d, a2, T1[2]); T1[3] = ffma2(w1d, a3, T1[3]);
                    T1[4] = ffma2(w1d, a4, T1[4]); T1[5] = ffma2(w1d, a5, T1[5]);
                }
                // vertex 0: cols cc=0..2 ; vertex 1: cols cc=3..5 (batch-pair bp, half)
                if (vg0 < VV) {
                    float2 c0 = unpack2(acc[0*4+bp]);
                    float2 c1 = unpack2(acc[1*4+bp]);
                    float2 c2 = unpack2(acc[2*4+bp]);
                    float x = (half ? c0.y : c0.x) + s_vt[cgrp*6+0];
                    float y = (half ? c1.y : c1.x) + s_vt[cgrp*6+1];
                    float z = (half ? c2.y : c2.x) + s_vt[cgrp*6+2];
                    float2 r0 = unpack2(T0[0]), r1 = unpack2(T0[1]);
                    float2 r2 = unpack2(T0[2]), r3 = unpack2(T0[3]);
                    float2 r4 = unpack2(T0[4]), r5 = unpack2(T0[5]);
                    float* o = out + (size_t)b*VC + vg0*3;
                    o[0] = r0.x*x + r0.y*y + r1.x*z + r1.y;
                    o[1] = r2.x*x + r2.y*y + r3.x*z + r3.y;
                    o[2] = r4.x*x + r4.y*y + r5.x*z + r5.y;
                }
                if (vg1 < VV) {
                    float2 c3 = unpack2(acc[3*4+bp]);
                    float2 c4 = unpack2(acc[4*4+bp]);
                    float2 c5 = unpack2(acc[5*4+bp]);
                    float x = (half ? c3.y : c3.x) + s_vt[cgrp*6+3];
                    float y = (half ? c4.y : c4.x) + s_vt[cgrp*6+4];
                    float z = (half ? c5.y : c5.x) + s_vt[cgrp*6+5];
                    float2 r0 = unpack2(T1[0]), r1 = unpack2(T1[1]);
                    float2 r2 = unpack2(T1[2]), r3 = unpack2(T1[3]);
                    float2 r4 = unpack2(T1[4]), r5 = unpack2(T1[5]);
                    float* o = out + (size_t)b*VC + vg1*3;
                    o[0] = r0.x*x + r0.y*y + r1.x*z + r1.y;
                    o[1] = r2.x*x + r2.y*y + r3.x*z + r3.y;
                    o[2] = r4.x*x + r4.y*y + r5.x*z + r5.y;
                }
            }
        }
    }
}

// ---------------------------------------------------------------------------
// Kernel 3: joints = vertices @ joint_regressor (deterministic 2-stage)
// ---------------------------------------------------------------------------
__global__ void __launch_bounds__(256) k_jnt_part(const float* __restrict__ outv,
                                                  const float* __restrict__ jreg)
{
    __shared__ float s_jr[512 * NJO];
    const int chunk = blockIdx.x;
    const int v0 = chunk * 512;
    for (int i = threadIdx.x; i < 512*NJO; i += 256) {
        int v = v0 + i / NJO;
        s_jr[i] = (v < VV) ? jreg[v*NJO + (i % NJO)] : 0.f;
    }
    __syncthreads();

    const int bl = threadIdx.x >> 5, lane = threadIdx.x & 31;
    const int b = blockIdx.y * 8 + bl;

    float acc[57];
    #pragma unroll
    for (int i = 0; i < 57; ++i) acc[i] = 0.f;

    #pragma unroll 4
    for (int i = 0; i < 16; ++i) {
        int vl = lane + i*32;
        int vg = v0 + vl;
        if (vg < VV) {
            const float* p = outv + (size_t)b*VC + vg*3;
            float x = p[0], y = p[1], z = p[2];
            #pragma unroll
            for (int j = 0; j < NJO; ++j) {
                float r = s_jr[vl*NJO + j];
                acc[j*3+0] = fmaf(r, x, acc[j*3+0]);
                acc[j*3+1] = fmaf(r, y, acc[j*3+1]);
                acc[j*3+2] = fmaf(r, z, acc[j*3+2]);
            }
        }
    }
    #pragma unroll
    for (int m = 16; m > 0; m >>= 1)
        #pragma unroll
        for (int i = 0; i < 57; ++i)
            acc[i] += __shfl_xor_sync(0xffffffffu, acc[i], m);

    if (lane == 0) {
        float* dst = g_jpart + (size_t)(b*14 + chunk)*57;
        #pragma unroll
        for (int i = 0; i < 57; ++i) dst[i] = acc[i];
    }
}

__global__ void k_jnt_red(float* __restrict__ out)
{
    int i = blockIdx.x * blockDim.x + threadIdx.x;
    if (i < BB * 57) {
        int b = i / 57, r = i % 57;
        float t = 0.f;
        #pragma unroll
        for (int p = 0; p < 14; ++p) t += g_jpart[(size_t)(b*14 + p)*57 + r];
        out[JNT_OFF + i] = t;
    }
}

// ---------------------------------------------------------------------------
extern "C" void kernel_launch(void* const* d_in, const int* in_sizes, int n_in,
                              void* d_out, int out_size)
{
    const float* inputs   = (const float*)d_in[0];
    const float* v_templ  = (const float*)d_in[1];
    const float* shapes   = (const float*)d_in[2];
    const float* posedirs = (const float*)d_in[3];
    const float* smpl_reg = (const float*)d_in[4];
    const float* lbs_w    = (const float*)d_in[5];
    const float* joint_rg = (const float*)d_in[6];
    float* out = (float*)d_out;

    k_jm<<<dim3(NJ, 8), 128>>>(v_templ, shapes, smpl_reg);
    k_jmred<<<4, 256>>>();

    k_rotchain<<<16, 96>>>(inputs, out);

    k_main<<<dim3(216, 8), 128>>>(posedirs, shapes, lbs_w, v_templ, out);

    k_jnt_part<<<dim3(14, 64), 256>>>(out, joint_rg);
    k_jnt_red<<<(BB*57 + 255)/256, 256>>>(out);
}

// round 5
// speedup vs baseline: 1.3021x; 1.3021x over previous
#include <cuda_runtime.h>
#include <cuda_bf16.h>
#include <math.h>

// ---------------------------------------------------------------------------
#define BB 512
#define VV 6890
#define NJ 24
#define NBETA 10
#define NP 207
#define NJO 19
#define VC (VV*3)              // 20670
#define KTOT 217
#define KPAD 224               // 7*32
#define JNT_OFF  (BB*VC)
#define ROT_OFF  (JNT_OFF + BB*NJO*3)

typedef unsigned long long u64;

__device__ __forceinline__ u64 ffma2(u64 a, u64 b, u64 c) {
    u64 d;
    asm("fma.rn.f32x2 %0, %1, %2, %3;" : "=l"(d) : "l"(a), "l"(b), "l"(c));
    return d;
}
__device__ __forceinline__ u64 pack2(float lo, float hi) {
    u64 d;
    asm("mov.b64 %0, {%1, %2};" : "=l"(d) : "f"(lo), "f"(hi));
    return d;
}
__device__ __forceinline__ float2 unpack2(u64 v) {
    float2 f;
    asm("mov.b64 {%0, %1}, %2;" : "=f"(f.x), "=f"(f.y) : "l"(v));
    return f;
}
__device__ __forceinline__ void cp_async8(unsigned saddr, const void* gaddr, int srcsize) {
    asm volatile("cp.async.ca.shared.global [%0], [%1], 8, %2;"
                 :: "r"(saddr), "l"(gaddr), "r"(srcsize));
}
__device__ __forceinline__ void cp_async16(unsigned saddr, const void* gaddr) {
    asm volatile("cp.async.ca.shared.global [%0], [%1], 16;"
                 :: "r"(saddr), "l"(gaddr));
}
__device__ __forceinline__ void cp_commit() {
    asm volatile("cp.async.commit_group;");
}
template<int N>
__device__ __forceinline__ void cp_wait() {
    asm volatile("cp.async.wait_group %0;" :: "n"(N));
}

// ---------------------------------------------------------------------------
__device__ float g_pfT[KPAD * BB];        // pose-feature+beta, [k][b]
__device__ float g_A[BB * NJ * 12];       // A' 3x4 per (b,j)
__device__ float g_jmp[NJ * 8 * 33];
__device__ float g_jm[NJ * 33];
__device__ float g_jpart[BB * 14 * 57];

// ---------------------------------------------------------------------------
// Kernel 0: batch-independent precompute for rest joints
// ---------------------------------------------------------------------------
__global__ void __launch_bounds__(128) k_jm(const float* __restrict__ vt,
                                            const float* __restrict__ shp,
                                            const float* __restrict__ sr)
{
    int j = blockIdx.x, part = blockIdx.y;
    int vs = part * 862;
    int ve = vs + 862; if (ve > VV) ve = VV;

    float acc[33];
    #pragma unroll
    for (int i = 0; i < 33; ++i) acc[i] = 0.f;

    for (int v = vs + threadIdx.x; v < ve; v += 128) {
        float w = sr[v * NJ + j];
        acc[0] += vt[v*3+0] * w;
        acc[1] += vt[v*3+1] * w;
        acc[2] += vt[v*3+2] * w;
        #pragma unroll
        for (int k = 0; k < NBETA; ++k) {
            const float* s = shp + k * VC + v * 3;
            acc[3+k*3+0] += s[0] * w;
            acc[3+k*3+1] += s[1] * w;
            acc[3+k*3+2] += s[2] * w;
        }
    }
    #pragma unroll
    for (int m = 16; m > 0; m >>= 1)
        #pragma unroll
        for (int i = 0; i < 33; ++i)
            acc[i] += __shfl_xor_sync(0xffffffffu, acc[i], m);

    __shared__ float s[4][33];
    int wid = threadIdx.x >> 5, lane = threadIdx.x & 31;
    if (lane == 0)
        #pragma unroll
        for (int i = 0; i < 33; ++i) s[wid][i] = acc[i];
    __syncthreads();
    if (threadIdx.x < 33) {
        float t = s[0][threadIdx.x] + s[1][threadIdx.x] + s[2][threadIdx.x] + s[3][threadIdx.x];
        g_jmp[(j*8 + part)*33 + threadIdx.x] = t;
    }
}

__global__ void k_jmred()
{
    int i = blockIdx.x * blockDim.x + threadIdx.x;
    if (i < NJ * 33) {
        int jj = i / 33, r = i % 33;
        float t = 0.f;
        #pragma unroll
        for (int p = 0; p < 8; ++p) t += g_jmp[(jj*8 + p)*33 + r];
        g_jm[i] = t;
    }
}

// ---------------------------------------------------------------------------
// Kernel 1: fused Rodrigues + kinematic chain. 32 batches per block.
// ---------------------------------------------------------------------------
__global__ void __launch_bounds__(96) k_rotchain(const float* __restrict__ inp,
                                                 float* __restrict__ out)
{
    const int PAR[NJ] = {0,0,0,0,1,2,3,4,5,6,7,8,9,9,9,12,13,14,16,17,18,19,20,21};
    __shared__ float s_jm[NJ * 33];
    __shared__ float sJ[32][NJ*3];
    __shared__ float sR[32][NJ*9];

    const int tid = threadIdx.x;
    const int b0 = blockIdx.x * 32;

    for (int i = tid; i < NJ*33; i += 96) s_jm[i] = g_jm[i];

    for (int i = tid; i < 32*NJ; i += 96) {
        int bl = i / NJ, j = i % NJ;
        int b = b0 + bl;
        float rx = inp[b*82 + j*3 + 0];
        float ry = inp[b*82 + j*3 + 1];
        float rz = inp[b*82 + j*3 + 2];
        float ax = rx + 1e-8f, ay = ry + 1e-8f, az = rz + 1e-8f;
        float ang = sqrtf(ax*ax + ay*ay + az*az);
        float inv = 1.0f / ang;
        float nx = rx * inv, ny = ry * inv, nz = rz * inv;
        float c = cosf(ang), sn = sinf(ang), ic = 1.0f - c;
        float R[9];
        R[0] = c + ic*nx*nx;     R[1] = ic*nx*ny - sn*nz; R[2] = ic*nx*nz + sn*ny;
        R[3] = ic*ny*nx + sn*nz; R[4] = c + ic*ny*ny;     R[5] = ic*ny*nz - sn*nx;
        R[6] = ic*nz*nx - sn*ny; R[7] = ic*nz*ny + sn*nx; R[8] = c + ic*nz*nz;

        float* ro = out + ROT_OFF + (size_t)b*(NJ*9) + j*9;
        #pragma unroll
        for (int e = 0; e < 9; ++e) { ro[e] = R[e]; sR[bl][j*9+e] = R[e]; }

        if (j > 0) {
            int base = (j-1) * 9;
            #pragma unroll
            for (int e = 0; e < 9; ++e)
                g_pfT[(base + e) * BB + b] = R[e] - ((e==0||e==4||e==8) ? 1.0f : 0.0f);
        }
    }
    __syncthreads();

    for (int i = tid; i < 32*NJ*3; i += 96) {
        int bl = i / 72, rem = i % 72;
        int j = rem / 3, c = rem % 3;
        int b = b0 + bl;
        float t = s_jm[j*33 + c];
        #pragma unroll
        for (int k = 0; k < NBETA; ++k)
            t = fmaf(inp[b*82 + 72 + k], s_jm[j*33 + 3 + k*3 + c], t);
        sJ[bl][j*3 + c] = t;
    }
    __syncthreads();

    const int bl = tid / 3;
    const int r  = tid % 3;
    const int b  = b0 + bl;
    const float* Rb = sR[bl];

    float row[NJ][3];
    float tw[NJ];
    row[0][0] = Rb[r*3+0]; row[0][1] = Rb[r*3+1]; row[0][2] = Rb[r*3+2];
    tw[0] = sJ[bl][r];

    #pragma unroll
    for (int j = 1; j < NJ; ++j) {
        const int p = PAR[j];
        float t0 = sJ[bl][j*3+0] - sJ[bl][p*3+0];
        float t1 = sJ[bl][j*3+1] - sJ[bl][p*3+1];
        float t2 = sJ[bl][j*3+2] - sJ[bl][p*3+2];
        float p0 = row[p][0], p1 = row[p][1], p2 = row[p][2];
        row[j][0] = p0*Rb[j*9+0] + p1*Rb[j*9+3] + p2*Rb[j*9+6];
        row[j][1] = p0*Rb[j*9+1] + p1*Rb[j*9+4] + p2*Rb[j*9+7];
        row[j][2] = p0*Rb[j*9+2] + p1*Rb[j*9+5] + p2*Rb[j*9+8];
        tw[j] = p0*t0 + p1*t1 + p2*t2 + tw[p];
    }

    float* Ao = g_A + (size_t)b * (NJ*12);
    #pragma unroll
    for (int j = 0; j < NJ; ++j) {
        float tp = tw[j] - (row[j][0]*sJ[bl][j*3+0] + row[j][1]*sJ[bl][j*3+1] + row[j][2]*sJ[bl][j*3+2]);
        float4 st = make_float4(row[j][0], row[j][1], row[j][2], tp);
        *reinterpret_cast<float4*>(&Ao[j*12 + r*4]) = st;
    }

    if (r == 0) {
        #pragma unroll
        for (int k = 0; k < NBETA; ++k) g_pfT[(NP + k)*BB + b] = inp[b*82 + 72 + k];
        #pragma unroll
        for (int k = KTOT; k < KPAD; ++k) g_pfT[k*BB + b] = 0.0f;
    }
}

// ---------------------------------------------------------------------------
// Kernel 2: fused blendshape GEMM + LBS skinning.
// Tile: 64 batches x 96 cols, 128 threads, cp.async double-buffered stages.
//   cgrp in 0..15 -> 6 cols (2 verts); bgrp in 0..7.
//   Batch pairs per thread: (2*bgrp + 16*bp, +1) for bp=0..3 — strided so
//   each epilogue pass (32 staged batches) keeps ALL threads active.
// d stored natural in smem; duplicated per-k in registers (pack2).
// ---------------------------------------------------------------------------
__global__ void __launch_bounds__(128, 4) k_main(const float* __restrict__ posedirs,
                                                 const float* __restrict__ shapes,
                                                 const float* __restrict__ lbs,
                                                 const float* __restrict__ vtempl,
                                                 float* __restrict__ out)
{
    __shared__ __align__(16) float smem[10240];   // 40 KB
    float* s_d  = smem;          // 2 x [32][96]
    float* s_pf = smem + 6144;   // 2 x [32][64]

    const int b0   = blockIdx.y * 64;
    const int col0 = blockIdx.x * 96;
    const int v0   = blockIdx.x * 32;
    const int tid  = threadIdx.x;
    const int lane = tid & 31;
    const int warp = tid >> 5;
    const int cgrp = (lane & 7) + ((warp & 1) << 3);   // 0..15
    const int bgrp = (lane >> 3) + ((warp >> 1) << 2); // 0..7

    const unsigned sd_base  = (unsigned)__cvta_generic_to_shared(s_d);
    const unsigned spf_base = (unsigned)__cvta_generic_to_shared(s_pf);

    // tile loader: kt in 0..6 into stage buf
    auto load_tiles = [&](int kt, int buf) {
        #pragma unroll
        for (int it = 0; it < 12; ++it) {
            int i = tid + it*128;
            int k = i / 48, q = i % 48;
            int kg = kt*32 + k;
            int cg = col0 + q*2;
            const float* src = posedirs;
            int sz = 0;
            if (cg < VC && kg < KTOT) {
                sz = 8;
                src = (kg < NP) ? posedirs + (size_t)kg*VC + cg
                                : shapes + (size_t)(kg-NP)*VC + cg;
            }
            cp_async8(sd_base + (unsigned)(buf*3072 + k*96 + q*2)*4u, src, sz);
        }
        #pragma unroll
        for (int it = 0; it < 4; ++it) {
            int i = tid + it*128;
            int k = i >> 4, q = i & 15;
            cp_async16(spf_base + (unsigned)(buf*2048 + k*64 + q*4)*4u,
                       &g_pfT[(kt*32 + k)*BB + b0 + q*4]);
        }
        cp_commit();
    };

    u64 acc[24];                       // [cc*4+bp], packs batch pair (lo,hi)
    const u64 z2 = pack2(0.f, 0.f);
    #pragma unroll
    for (int i = 0; i < 24; ++i) acc[i] = z2;

    load_tiles(0, 0);

    for (int kt = 0; kt < 7; ++kt) {
        const int buf = kt & 1;
        if (kt < 6) load_tiles(kt+1, buf ^ 1);
        if (kt < 6) cp_wait<1>(); else cp_wait<0>();
        __syncthreads();

        const float* dbase = s_d + buf*3072 + cgrp*6;
        const u64*   pfb   = reinterpret_cast<const u64*>(s_pf + buf*2048) + bgrp;

        #pragma unroll
        for (int k = 0; k < 32; ++k) {
            float2 d01 = *reinterpret_cast<const float2*>(dbase + k*96 + 0);
            float2 d23 = *reinterpret_cast<const float2*>(dbase + k*96 + 2);
            float2 d45 = *reinterpret_cast<const float2*>(dbase + k*96 + 4);
            u64 dd0 = pack2(d01.x, d01.x), dd1 = pack2(d01.y, d01.y);
            u64 dd2 = pack2(d23.x, d23.x), dd3 = pack2(d23.y, d23.y);
            u64 dd4 = pack2(d45.x, d45.x), dd5 = pack2(d45.y, d45.y);
            u64 p0 = pfb[k*32 + 0];
            u64 p1 = pfb[k*32 + 8];
            u64 p2 = pfb[k*32 + 16];
            u64 p3 = pfb[k*32 + 24];
            acc[0]  = ffma2(p0, dd0, acc[0]);
            acc[1]  = ffma2(p1, dd0, acc[1]);
            acc[2]  = ffma2(p2, dd0, acc[2]);
            acc[3]  = ffma2(p3, dd0, acc[3]);
            acc[4]  = ffma2(p0, dd1, acc[4]);
            acc[5]  = ffma2(p1, dd1, acc[5]);
            acc[6]  = ffma2(p2, dd1, acc[6]);
            acc[7]  = ffma2(p3, dd1, acc[7]);
            acc[8]  = ffma2(p0, dd2, acc[8]);
            acc[9]  = ffma2(p1, dd2, acc[9]);
            acc[10] = ffma2(p2, dd2, acc[10]);
            acc[11] = ffma2(p3, dd2, acc[11]);
            acc[12] = ffma2(p0, dd3, acc[12]);
            acc[13] = ffma2(p1, dd3, acc[13]);
            acc[14] = ffma2(p2, dd3, acc[14]);
            acc[15] = ffma2(p3, dd3, acc[15]);
            acc[16] = ffma2(p0, dd4, acc[16]);
            acc[17] = ffma2(p1, dd4, acc[17]);
            acc[18] = ffma2(p2, dd4, acc[18]);
            acc[19] = ffma2(p3, dd4, acc[19]);
            acc[20] = ffma2(p0, dd5, acc[20]);
            acc[21] = ffma2(p1, dd5, acc[21]);
            acc[22] = ffma2(p2, dd5, acc[22]);
            acc[23] = ffma2(p3, dd5, acc[23]);
        }
        __syncthreads();
    }

    // ---- epilogue ----
    float* s_w  = smem + 9216;   // [32 verts][24]
    float* s_vt = smem + 9984;   // [96]
    for (int i = tid; i < 768; i += 128) {
        int v = v0 + i/24;
        s_w[i] = (v < VV) ? lbs[v*NJ + (i % 24)] : 0.f;
    }
    if (tid < 96) {
        int cg = col0 + tid;
        s_vt[tid] = (cg < VC) ? vtempl[cg] : 0.f;
    }

    const int v0l = cgrp * 2;
    const int vg0 = v0 + v0l;
    const int vg1 = vg0 + 1;

    #pragma unroll
    for (int pass = 0; pass < 2; ++pass) {
        __syncthreads();
        const float4* gA4 = reinterpret_cast<const float4*>(g_A + (size_t)(b0 + pass*32)*288);
        #pragma unroll
        for (int i = 0; i < 18; ++i)
            reinterpret_cast<float4*>(smem)[tid + 128*i] = gA4[tid + 128*i];
        __syncthreads();

        #pragma unroll
        for (int bpi = 0; bpi < 2; ++bpi) {
            const int bp = pass*2 + bpi;
            #pragma unroll
            for (int half = 0; half < 2; ++half) {
                const int ab = 2*bgrp + 16*bpi + half;
                const int b = b0 + pass*32 + ab;
                const u64* Ar = reinterpret_cast<const u64*>(smem + ab*288);
                u64 T0[6], T1[6];
                #pragma unroll
                for (int i = 0; i < 6; ++i) { T0[i] = z2; T1[i] = z2; }
                #pragma unroll
                for (int j = 0; j < NJ; ++j) {
                    u64 a0 = Ar[j*6+0], a1 = Ar[j*6+1], a2 = Ar[j*6+2];
                    u64 a3 = Ar[j*6+3], a4 = Ar[j*6+4], a5 = Ar[j*6+5];
                    float w0 = s_w[(v0l+0)*24 + j];
                    float w1 = s_w[(v0l+1)*24 + j];
                    u64 w0d = pack2(w0, w0);
                    u64 w1d = pack2(w1, w1);
                    T0[0] = ffma2(w0d, a0, T0[0]); T0[1] = ffma2(w0d, a1, T0[1]);
                    T0[2] = ffma2(w0d, a2, T0[2]); T0[3] = ffma2(w0d, a3, T0[3]);
                    T0[4] = ffma2(w0d, a4, T0[4]); T0[5] = ffma2(w0d, a5, T0[5]);
                    T1[0] = ffma2(w1d, a0, T1[0]); T1[1] = ffma2(w1d, a1, T1[1]);
                    T1[2] = ffma2(w1d, a2, T1[2]); T1[3] = ffma2(w1d, a3, T1[3]);
                    T1[4] = ffma2(w1d, a4, T1[4]); T1[5] = ffma2(w1d, a5, T1[5]);
                }
                if (vg0 < VV) {
                    float2 c0 = unpack2(acc[0*4+bp]);
                    float2 c1 = unpack2(acc[1*4+bp]);
                    float2 c2 = unpack2(acc[2*4+bp]);
                    float x = (half ? c0.y : c0.x) + s_vt[cgrp*6+0];
                    float y = (half ? c1.y : c1.x) + s_vt[cgrp*6+1];
                    float z = (half ? c2.y : c2.x) + s_vt[cgrp*6+2];
                    float2 r0 = unpack2(T0[0]), r1 = unpack2(T0[1]);
                    float2 r2 = unpack2(T0[2]), r3 = unpack2(T0[3]);
                    float2 r4 = unpack2(T0[4]), r5 = unpack2(T0[5]);
                    float* o = out + (size_t)b*VC + vg0*3;
                    o[0] = r0.x*x + r0.y*y + r1.x*z + r1.y;
                    o[1] = r2.x*x + r2.y*y + r3.x*z + r3.y;
                    o[2] = r4.x*x + r4.y*y + r5.x*z + r5.y;
                }
                if (vg1 < VV) {
                    float2 c3 = unpack2(acc[3*4+bp]);
                    float2 c4 = unpack2(acc[4*4+bp]);
                    float2 c5 = unpack2(acc[5*4+bp]);
                    float x = (half ? c3.y : c3.x) + s_vt[cgrp*6+3];
                    float y = (half ? c4.y : c4.x) + s_vt[cgrp*6+4];
                    float z = (half ? c5.y : c5.x) + s_vt[cgrp*6+5];
                    float2 r0 = unpack2(T1[0]), r1 = unpack2(T1[1]);
                    float2 r2 = unpack2(T1[2]), r3 = unpack2(T1[3]);
                    float2 r4 = unpack2(T1[4]), r5 = unpack2(T1[5]);
                    float* o = out + (size_t)b*VC + vg1*3;
                    o[0] = r0.x*x + r0.y*y + r1.x*z + r1.y;
                    o[1] = r2.x*x + r2.y*y + r3.x*z + r3.y;
                    o[2] = r4.x*x + r4.y*y + r5.x*z + r5.y;
                }
            }
        }
    }
}

// ---------------------------------------------------------------------------
// Kernel 3: joints = vertices @ joint_regressor (deterministic 2-stage)
// ---------------------------------------------------------------------------
__global__ void __launch_bounds__(256) k_jnt_part(const float* __restrict__ outv,
                                                  const float* __restrict__ jreg)
{
    __shared__ float s_jr[512 * NJO];
    const int chunk = blockIdx.x;
    const int v0 = chunk * 512;
    for (int i = threadIdx.x; i < 512*NJO; i += 256) {
        int v = v0 + i / NJO;
        s_jr[i] = (v < VV) ? jreg[v*NJO + (i % NJO)] : 0.f;
    }
    __syncthreads();

    const int bl = threadIdx.x >> 5, lane = threadIdx.x & 31;
    const int b = blockIdx.y * 8 + bl;

    float acc[57];
    #pragma unroll
    for (int i = 0; i < 57; ++i) acc[i] = 0.f;

    #pragma unroll 4
    for (int i = 0; i < 16; ++i) {
        int vl = lane + i*32;
        int vg = v0 + vl;
        if (vg < VV) {
            const float* p = outv + (size_t)b*VC + vg*3;
            float x = p[0], y = p[1], z = p[2];
            #pragma unroll
            for (int j = 0; j < NJO; ++j) {
                float r = s_jr[vl*NJO + j];
                acc[j*3+0] = fmaf(r, x, acc[j*3+0]);
                acc[j*3+1] = fmaf(r, y, acc[j*3+1]);
                acc[j*3+2] = fmaf(r, z, acc[j*3+2]);
            }
        }
    }
    #pragma unroll
    for (int m = 16; m > 0; m >>= 1)
        #pragma unroll
        for (int i = 0; i < 57; ++i)
            acc[i] += __shfl_xor_sync(0xffffffffu, acc[i], m);

    if (lane == 0) {
        float* dst = g_jpart + (size_t)(b*14 + chunk)*57;
        #pragma unroll
        for (int i = 0; i < 57; ++i) dst[i] = acc[i];
    }
}

__global__ void k_jnt_red(float* __restrict__ out)
{
    int i = blockIdx.x * blockDim.x + threadIdx.x;
    if (i < BB * 57) {
        int b = i / 57, r = i % 57;
        float t = 0.f;
        #pragma unroll
        for (int p = 0; p < 14; ++p) t += g_jpart[(size_t)(b*14 + p)*57 + r];
        out[JNT_OFF + i] = t;
    }
}

// ---------------------------------------------------------------------------
extern "C" void kernel_launch(void* const* d_in, const int* in_sizes, int n_in,
                              void* d_out, int out_size)
{
    const float* inputs   = (const float*)d_in[0];
    const float* v_templ  = (const float*)d_in[1];
    const float* shapes   = (const float*)d_in[2];
    const float* posedirs = (const float*)d_in[3];
    const float* smpl_reg = (const float*)d_in[4];
    const float* lbs_w    = (const float*)d_in[5];
    const float* joint_rg = (const float*)d_in[6];
    float* out = (float*)d_out;

    k_jm<<<dim3(NJ, 8), 128>>>(v_templ, shapes, smpl_reg);
    k_jmred<<<4, 256>>>();

    k_rotchain<<<16, 96>>>(inputs, out);

    k_main<<<dim3(216, 8), 128>>>(posedirs, shapes, lbs_w, v_templ, out);

    k_jnt_part<<<dim3(14, 64), 256>>>(out, joint_rg);
    k_jnt_red<<<(BB*57 + 255)/256, 256>>>(out);
}